// round 4
// baseline (speedup 1.0000x reference)
#include <cuda_runtime.h>
#include <cstdint>

#define TT   512
#define BB   128
#define LATN 1024
#define DIMX 256
#define BM   64
#define BN   16
#define BK   64
#define SAR  66
#define SAW  66
#define NT   512

typedef unsigned long long ull;

// counters: [mi][chunk][zgroup][pad16] -> sub-counters 64B apart, chunks 256B apart
__device__ unsigned g_cnt[2][8][4][16];

__device__ __forceinline__ ull fma2(ull a, ull b, ull c) {
    ull d; asm("fma.rn.f32x2 %0, %1, %2, %3;" : "=l"(d) : "l"(a), "l"(b), "l"(c)); return d;
}
__device__ __forceinline__ ull add2(ull a, ull b) {
    ull d; asm("add.rn.f32x2 %0, %1, %2;" : "=l"(d) : "l"(a), "l"(b)); return d;
}
__device__ __forceinline__ float2 unp2(ull v) {
    float2 f; asm("mov.b64 {%0, %1}, %2;" : "=f"(f.x), "=f"(f.y) : "l"(v)); return f;
}
__device__ __forceinline__ unsigned ldrelax(const unsigned* p) {
    unsigned v; asm volatile("ld.relaxed.gpu.u32 %0, [%1];" : "=r"(v) : "l"(p) : "memory"); return v;
}

__global__ void __launch_bounds__(NT, 1)
rnn_persist(const float* __restrict__ x, const float* __restrict__ W,
            const float* __restrict__ b, float* __restrict__ out)
{
    __shared__ float sA[2][BM * SAR];    // 33792 B
    __shared__ float sWt[2][BN * SAW];   //  8448 B   (total 42240 B)

    const int tid  = threadIdx.x;
    const int cta  = blockIdx.x;
    const int mi   = cta & 1;            // M-half
    const int nj   = cta >> 1;           // N-tile 0..63
    const int m0   = mi * BM;
    const int n0   = nj * BN;
    const int sub  = nj >> 3;            // 128-col chunk this CTA produces

    const int lane = tid & 31;
    const int tm   = tid >> 5;           // warp id 0..15 -> rows 4tm..4tm+3
    const int tn   = lane & 7;           // col pair n0+2tn+{0,1}
    const int z    = lane >> 3;          // k-pair interleave class 0..3

    const int lm   = tid >> 4;           // a-loader row (and +32)
    const int lk4  = tid & 15;           // a-loader k-quad
    const int wk   = tid >> 2;           // w-loader k row (tid<256)
    const int wnq  = tid & 3;            // w-loader n-quad

    const float b0 = b[n0 + 2 * tn];
    const float b1 = b[n0 + 2 * tn + 1];

    long long budget = 1LL << 22;

    float4 va0, va1, wv;

#define LDG_TILE(kt_, t_)                                                     \
  { const int _kt = (kt_);                                                    \
    if (tid < 256)                                                            \
      wv = *(const float4*)(W + (size_t)(_kt * BK + wk) * LATN + n0 + 4 * wnq); \
    if (_kt < 4) {                                                            \
      const float* _p = x + (size_t)(m0 + lm) * (TT * DIMX)                   \
                          + (size_t)(t_) * DIMX + _kt * BK + 4 * lk4;         \
      va0 = __ldcs((const float4*)_p);                                        \
      va1 = __ldcs((const float4*)(_p + 32 * (TT * DIMX)));                   \
    } else {                                                                  \
      const float* _p = out + (size_t)((t_) - 1) * (BB * LATN)                \
                            + (size_t)(m0 + lm) * LATN + (_kt - 4) * BK + 4 * lk4; \
      va0 = __ldcs((const float4*)_p);                                        \
      va1 = __ldcs((const float4*)(_p + 32 * LATN));                          \
    } }

#define STS_TILE(buf_)                                                        \
  { float* _a0 = &sA[buf_][lm * SAR + 4 * lk4];                               \
    float* _a1 = &sA[buf_][(lm + 32) * SAR + 4 * lk4];                        \
    *(float2*)(_a0)     = make_float2(va0.x, va0.y);                          \
    *(float2*)(_a0 + 2) = make_float2(va0.z, va0.w);                          \
    *(float2*)(_a1)     = make_float2(va1.x, va1.y);                          \
    *(float2*)(_a1 + 2) = make_float2(va1.z, va1.w);                          \
    if (tid < 256) {                                                          \
      float* _w = &sWt[buf_][0];                                              \
      _w[(4 * wnq + 0) * SAW + wk] = wv.x;                                    \
      _w[(4 * wnq + 1) * SAW + wk] = wv.y;                                    \
      _w[(4 * wnq + 2) * SAW + wk] = wv.z;                                    \
      _w[(4 * wnq + 3) * SAW + wk] = wv.w;                                    \
    } }

    // k-pairs: thread with class z handles k = 8j + 2z + {0,1}, j = 0..7
#define COMPUTE_TILE(buf_)                                                    \
  { const float* _a = &sA[buf_][4 * tm * SAR + 2 * z];                        \
    const float* _w = &sWt[buf_][2 * tn * SAW + 2 * z];                       \
    _Pragma("unroll")                                                         \
    for (int j = 0; j < 8; ++j) {                                             \
      ull A0 = *(const ull*)(_a + 8 * j);                                     \
      ull A1 = *(const ull*)(_a + SAR + 8 * j);                               \
      ull A2 = *(const ull*)(_a + 2 * SAR + 8 * j);                           \
      ull A3 = *(const ull*)(_a + 3 * SAR + 8 * j);                           \
      ull W0 = *(const ull*)(_w + 8 * j);                                     \
      ull W1 = *(const ull*)(_w + SAW + 8 * j);                               \
      ac00 = fma2(A0, W0, ac00);  ac01 = fma2(A0, W1, ac01);                  \
      ac10 = fma2(A1, W0, ac10);  ac11 = fma2(A1, W1, ac11);                  \
      ac20 = fma2(A2, W0, ac20);  ac21 = fma2(A2, W1, ac21);                  \
      ac30 = fma2(A3, W0, ac30);  ac31 = fma2(A3, W1, ac31);                  \
    } }

#define WAIT_CHUNK(c_, t_)                                                    \
  { if (tid == 0) {                                                           \
      const unsigned* _c = &g_cnt[mi][c_][0][0];                              \
      for (;;) {                                                              \
        unsigned _s = ldrelax(_c) + ldrelax(_c + 16)                          \
                    + ldrelax(_c + 32) + ldrelax(_c + 48);                    \
        if (_s >= 4096u * (unsigned)(t_) || budget <= 0) break;               \
        __nanosleep(64); --budget;                                            \
      }                                                                       \
    }                                                                         \
    __syncthreads(); }

#pragma unroll 1
    for (int t = 0; t < TT; ++t) {
        ull ac00 = 0, ac01 = 0, ac10 = 0, ac11 = 0;
        ull ac20 = 0, ac21 = 0, ac30 = 0, ac31 = 0;

        const int ntiles = (t == 0) ? 4 : 20;

        LDG_TILE(0, t);
#pragma unroll 1
        for (int kt = 0; kt < ntiles; ++kt) {
            STS_TILE(kt & 1);
            __syncthreads();
            if (kt + 1 < ntiles) {
                if (kt + 1 >= 4 && (((kt + 1) - 4) & 1) == 0)
                    WAIT_CHUNK(((kt + 1) - 4) >> 1, t);
                LDG_TILE(kt + 1, t);
            }
            COMPUTE_TILE(kt & 1);
        }

        // ---- in-register k-split reduction: butterfly over lane bits 3,4 ----
#pragma unroll
        for (int d = 8; d <= 16; d <<= 1) {
            ac00 = add2(ac00, __shfl_xor_sync(0xFFFFFFFFu, ac00, d));
            ac01 = add2(ac01, __shfl_xor_sync(0xFFFFFFFFu, ac01, d));
            ac10 = add2(ac10, __shfl_xor_sync(0xFFFFFFFFu, ac10, d));
            ac11 = add2(ac11, __shfl_xor_sync(0xFFFFFFFFu, ac11, d));
            ac20 = add2(ac20, __shfl_xor_sync(0xFFFFFFFFu, ac20, d));
            ac21 = add2(ac21, __shfl_xor_sync(0xFFFFFFFFu, ac21, d));
            ac30 = add2(ac30, __shfl_xor_sync(0xFFFFFFFFu, ac30, d));
            ac31 = add2(ac31, __shfl_xor_sync(0xFFFFFFFFu, ac31, d));
        }

        // ---- epilogue: lane class z stores row 4tm+z, cols n0+2tn+{0,1} ----
        {
            ull sa = (z == 0) ? ac00 : (z == 1) ? ac10 : (z == 2) ? ac20 : ac30;
            ull sb = (z == 0) ? ac01 : (z == 1) ? ac11 : (z == 2) ? ac21 : ac31;
            float2 ra = unp2(sa);
            float2 rb = unp2(sb);
            float v0 = tanhf(ra.x + ra.y + b0);
            float v1 = tanhf(rb.x + rb.y + b1);
            float* o = out + (size_t)t * (BB * LATN)
                           + (size_t)(m0 + 4 * tm + z) * LATN + n0 + 2 * tn;
            *(float2*)o = make_float2(v0, v1);
            // publish: release-increment orders THIS thread's store before the count
            asm volatile("red.release.gpu.add.u32 [%0], %1;"
                         :: "l"(&g_cnt[mi][sub][z][0]), "r"(1u) : "memory");
        }
    }

    // ---- reset counters for next graph replay ----
    if (tid == 0 && (nj & 7) == 0) {
        unsigned* c = &g_cnt[mi][sub][0][0];
        for (;;) {
            unsigned s = ldrelax(c) + ldrelax(c + 16) + ldrelax(c + 32) + ldrelax(c + 48);
            if (s >= 4096u * (unsigned)TT || budget <= 0) break;
            __nanosleep(64); --budget;
        }
        asm volatile("st.relaxed.gpu.u32 [%0], %1;" :: "l"(c),      "r"(0u) : "memory");
        asm volatile("st.relaxed.gpu.u32 [%0], %1;" :: "l"(c + 16), "r"(0u) : "memory");
        asm volatile("st.relaxed.gpu.u32 [%0], %1;" :: "l"(c + 32), "r"(0u) : "memory");
        asm volatile("st.relaxed.gpu.u32 [%0], %1;" :: "l"(c + 48), "r"(0u) : "memory");
    }
}

extern "C" void kernel_launch(void* const* d_in, const int* in_sizes, int n_in,
                              void* d_out, int out_size)
{
    const float* x = (const float*)d_in[0];   // (128, 512, 256) f32
    const float* W = (const float*)d_in[1];   // (1280, 1024) f32
    const float* b = (const float*)d_in[2];   // (1024,) f32
    float* out = (float*)d_out;               // (512, 128, 1024) f32

    rnn_persist<<<128, NT>>>(x, W, b, out);
}